// round 15
// baseline (speedup 1.0000x reference)
#include <cuda_runtime.h>
#include <cuda_bf16.h>
#include <cstdint>

#define BQ 4096
#define NTOK 49
#define EMB 256
#define NHEADS 8
#define HD 32
#define MROWS (BQ*NTOK)   // 200704 = 128*1568
#define MTILES (MROWS/16) // 12544
#define SPAD 40           // bf16 row stride: conflict-free ldmatrix

// gemm1 smem: A hi/lo, double buffered
#define OFF_ALO 10240
#define BUF_BYTES 20480
#define SMEM_BYTES (2*BUF_BYTES)   // 40960

// attention smem: ONE head: Khi,Klo,Vhi,Vlo tiles of 64x40 bf16 (5120 B each)
#define ATTN_SMEM 20480

// Scratch (device globals: allocation-free), 16B aligned
__device__ __align__(16) float g_q[BQ*NHEADS*NTOK*HD];
__device__ __align__(16) float g_k[BQ*NHEADS*NTOK*HD];
__device__ __align__(16) float g_v[BQ*NHEADS*NTOK*HD];
__device__ __align__(16) float g_att[MROWS*EMB];
__device__ __align__(16) float g_cmb[64*NHEADS*NTOK*64];  // mask+bias, pad = -1e9

// Pre-permuted fragments (per-lane ldmatrix.x4 output -> direct LDG.128)
__device__ uint4 g_fq[48*16*2*32];        // qkv_w B-frags (786 KB)
__device__ uint4 g_fp[16*16*2*32];        // proj_w B-frags (256 KB)
__device__ uint4 g_fx[MTILES*16*2*32];    // x A-frags (205 MB)

// ---------------------------------------------------------------------------
// PTX helpers
// ---------------------------------------------------------------------------
__device__ __forceinline__ uint32_t smem_u32(const void* p) {
    uint32_t a;
    asm("{ .reg .u64 t; cvta.to.shared.u64 t, %1; cvt.u32.u64 %0, t; }"
        : "=r"(a) : "l"(p));
    return a;
}

__device__ __forceinline__ void ldm_x4(uint32_t& r0, uint32_t& r1,
                                       uint32_t& r2, uint32_t& r3, uint32_t addr) {
    asm volatile("ldmatrix.sync.aligned.m8n8.x4.shared.b16 {%0,%1,%2,%3}, [%4];"
                 : "=r"(r0), "=r"(r1), "=r"(r2), "=r"(r3) : "r"(addr));
}

__device__ __forceinline__ void ldm_x4_t(uint32_t& r0, uint32_t& r1,
                                         uint32_t& r2, uint32_t& r3, uint32_t addr) {
    asm volatile("ldmatrix.sync.aligned.m8n8.x4.trans.shared.b16 {%0,%1,%2,%3}, [%4];"
                 : "=r"(r0), "=r"(r1), "=r"(r2), "=r"(r3) : "r"(addr));
}

__device__ __forceinline__ void mma_bf16(float* c, uint32_t a0, uint32_t a1,
                                         uint32_t a2, uint32_t a3,
                                         uint32_t b0, uint32_t b1) {
    asm volatile(
        "mma.sync.aligned.m16n8k16.row.col.f32.bf16.bf16.f32 "
        "{%0,%1,%2,%3}, {%4,%5,%6,%7}, {%8,%9}, {%0,%1,%2,%3};"
        : "+f"(c[0]), "+f"(c[1]), "+f"(c[2]), "+f"(c[3])
        : "r"(a0), "r"(a1), "r"(a2), "r"(a3), "r"(b0), "r"(b1));
}

__device__ __forceinline__ uint32_t pack_bf2(float a, float b) {
    __nv_bfloat162 v = __floats2bfloat162_rn(a, b);
    return *reinterpret_cast<uint32_t*>(&v);
}

__device__ __forceinline__ void split2(float x0, float x1, uint32_t& hi, uint32_t& lo) {
    hi = pack_bf2(x0, x1);
    const __nv_bfloat162 hv = *reinterpret_cast<const __nv_bfloat162*>(&hi);
    lo = pack_bf2(x0 - __bfloat162float(hv.x), x1 - __bfloat162float(hv.y));
}

// ---------------------------------------------------------------------------
// Weight prep (B-operand fragments): block = one n16 tile, warp w -> ksteps
// w, w+8. Stores per-lane ldmatrix.x4 output with B lane addressing.
// ---------------------------------------------------------------------------
__global__ void __launch_bounds__(256)
prep_w(const float* __restrict__ W, uint4* __restrict__ outf)
{
    __shared__ __align__(16) __nv_bfloat16 ph[8][16*SPAD];
    __shared__ __align__(16) __nv_bfloat16 pl[8][16*SPAD];
    const int t    = blockIdx.x;
    const int wid  = threadIdx.x >> 5;
    const int lane = threadIdx.x & 31;
    const uint32_t uh = smem_u32(ph[wid]);
    const uint32_t ul = smem_u32(pl[wid]);
    const int row = lane >> 1, c8 = (lane & 1) * 8;

#pragma unroll
    for (int pass = 0; pass < 2; ++pass) {
        const int ks = wid + pass * 8;
        const float* p = W + (t*16 + row) * EMB + ks*16 + c8;
        const float4 v0 = ((const float4*)p)[0];
        const float4 v1 = ((const float4*)p)[1];
        uint32_t h[4], l[4];
        split2(v0.x, v0.y, h[0], l[0]);
        split2(v0.z, v0.w, h[1], l[1]);
        split2(v1.x, v1.y, h[2], l[2]);
        split2(v1.z, v1.w, h[3], l[3]);
        __nv_bfloat16* dh = ph[wid] + row*SPAD + c8;
        ((uint2*)dh)[0] = make_uint2(h[0], h[1]);
        ((uint2*)dh)[1] = make_uint2(h[2], h[3]);
        __nv_bfloat16* dl = pl[wid] + row*SPAD + c8;
        ((uint2*)dl)[0] = make_uint2(l[0], l[1]);
        ((uint2*)dl)[1] = make_uint2(l[2], l[3]);
        __syncwarp();

        const uint32_t aoff = (uint32_t)(((((lane>>4)<<3) + (lane&7)) * SPAD
                                          + (((lane>>3)&1)<<3)) * 2);
        uint32_t r0, r1, r2, r3;
        ldm_x4(r0, r1, r2, r3, uh + aoff);
        outf[((t*16 + ks)*2 + 0)*32 + lane] = make_uint4(r0, r1, r2, r3);
        ldm_x4(r0, r1, r2, r3, ul + aoff);
        outf[((t*16 + ks)*2 + 1)*32 + lane] = make_uint4(r0, r1, r2, r3);
        __syncwarp();
    }
}

// ---------------------------------------------------------------------------
// x prep (A-operand fragments): block = one m16 tile, warp w -> ksteps w, w+8.
// A-operand lane addressing (rows = lane&15, col half = (lane>>4)*8).
// ---------------------------------------------------------------------------
__global__ void __launch_bounds__(256)
prep_x(const float* __restrict__ X)
{
    __shared__ __align__(16) __nv_bfloat16 ph[8][16*SPAD];
    __shared__ __align__(16) __nv_bfloat16 pl[8][16*SPAD];
    const int t    = blockIdx.x;
    const int wid  = threadIdx.x >> 5;
    const int lane = threadIdx.x & 31;
    const uint32_t uh = smem_u32(ph[wid]);
    const uint32_t ul = smem_u32(pl[wid]);
    const int row = lane >> 1, c8 = (lane & 1) * 8;

#pragma unroll
    for (int pass = 0; pass < 2; ++pass) {
        const int ks = wid + pass * 8;
        const float* p = X + (t*16 + row) * EMB + ks*16 + c8;
        const float4 v0 = ((const float4*)p)[0];
        const float4 v1 = ((const float4*)p)[1];
        uint32_t h[4], l[4];
        split2(v0.x, v0.y, h[0], l[0]);
        split2(v0.z, v0.w, h[1], l[1]);
        split2(v1.x, v1.y, h[2], l[2]);
        split2(v1.z, v1.w, h[3], l[3]);
        __nv_bfloat16* dh = ph[wid] + row*SPAD + c8;
        ((uint2*)dh)[0] = make_uint2(h[0], h[1]);
        ((uint2*)dh)[1] = make_uint2(h[2], h[3]);
        __nv_bfloat16* dl = pl[wid] + row*SPAD + c8;
        ((uint2*)dl)[0] = make_uint2(l[0], l[1]);
        ((uint2*)dl)[1] = make_uint2(l[2], l[3]);
        __syncwarp();

        const uint32_t aoff = (uint32_t)(((lane & 15) * SPAD + ((lane >> 4) << 3)) * 2);
        uint32_t r0, r1, r2, r3;
        ldm_x4(r0, r1, r2, r3, uh + aoff);
        g_fx[((t*16 + ks)*2 + 0)*32 + lane] = make_uint4(r0, r1, r2, r3);
        ldm_x4(r0, r1, r2, r3, ul + aoff);
        g_fx[((t*16 + ks)*2 + 1)*32 + lane] = make_uint4(r0, r1, r2, r3);
        __syncwarp();
    }
}

// ---------------------------------------------------------------------------
// gemm0 (QKV): fragment streaming, CTA 96x96, 4 warps of 48x48.
// acc = 72 regs; B (3 n16 tiles) held, A streamed per m16 tile -> live regs
// ~120 => __launch_bounds__(128,4) = 16 warps/SM (was 12). No smem, no syncs.
// M-grain 96: grid.y = 2091, tail CTA clamps A-tile index & guards stores.
// ---------------------------------------------------------------------------
__global__ void __launch_bounds__(128, 4)
gemm0_frag(const float* __restrict__ bias)
{
    const int tid = threadIdx.x;
    const int wid = tid >> 5;
    const int lid = tid & 31;
    const int m0  = blockIdx.y * 96 + (wid >> 1) * 48;   // warp's first m row
    const int n0  = blockIdx.x * 96 + (wid & 1) * 48;    // warp's first n col
    const int mt  = m0 >> 4;                             // first of 3 m16 tiles
    const int nt  = n0 >> 4;                             // first of 3 n16 tiles

    float acc[3][6][4];
#pragma unroll
    for (int i = 0; i < 3; i++)
#pragma unroll
        for (int j = 0; j < 6; j++)
#pragma unroll
            for (int r = 0; r < 4; r++) acc[i][j][r] = 0.f;

    // clamp tile indices for the M-tail CTA (stores are guarded separately)
    int mti[3];
#pragma unroll
    for (int i = 0; i < 3; ++i) {
        const int t = mt + i;
        mti[i] = (t < MTILES) ? t : (MTILES - 1);
    }

    const uint4* __restrict__ Bx = g_fq + (size_t)nt * 1024 + lid;

#pragma unroll 4
    for (int ks = 0; ks < 16; ++ks) {
        uint4 bh[3], bl[3];
#pragma unroll
        for (int jt = 0; jt < 3; ++jt) {
            bh[jt] = Bx[(size_t)jt * 1024 + ks * 64];
            bl[jt] = Bx[(size_t)jt * 1024 + ks * 64 + 32];
        }
#pragma unroll
        for (int i = 0; i < 3; ++i) {
            const uint4* Ax = g_fx + (size_t)mti[i] * 1024 + ks * 64 + lid;
            const uint4 fh = Ax[0];
            const uint4 fl = Ax[32];
#pragma unroll
            for (int jt = 0; jt < 3; ++jt) {
                mma_bf16(acc[i][2*jt+0], fh.x, fh.y, fh.z, fh.w, bh[jt].x, bh[jt].y);
                mma_bf16(acc[i][2*jt+1], fh.x, fh.y, fh.z, fh.w, bh[jt].z, bh[jt].w);
                mma_bf16(acc[i][2*jt+0], fh.x, fh.y, fh.z, fh.w, bl[jt].x, bl[jt].y);
                mma_bf16(acc[i][2*jt+1], fh.x, fh.y, fh.z, fh.w, bl[jt].z, bl[jt].w);
                mma_bf16(acc[i][2*jt+0], fl.x, fl.y, fl.z, fl.w, bh[jt].x, bh[jt].y);
                mma_bf16(acc[i][2*jt+1], fl.x, fl.y, fl.z, fl.w, bh[jt].z, bh[jt].w);
            }
        }
    }

    // ---- scatter epilogue: q/k/v (q scaled), guard m < MROWS ----
#pragma unroll
    for (int i = 0; i < 3; ++i) {
#pragma unroll
        for (int j = 0; j < 6; ++j) {
            const int n = n0 + j * 8 + 2 * (lid & 3);
            const float b0 = bias[n], b1 = bias[n + 1];
#pragma unroll
            for (int half = 0; half < 2; ++half) {
                const int m = m0 + i * 16 + (lid >> 2) + half * 8;
                if (m < MROWS) {
                    float2 o;
                    o.x = acc[i][j][half*2+0] + b0;
                    o.y = acc[i][j][half*2+1] + b1;
                    const int bb  = m / NTOK;
                    const int nn  = m - bb * NTOK;
                    const int sel = n >> 8;
                    const int h   = (n >> 5) & 7;
                    const int d   = n & 31;
                    if (sel == 0) { o.x *= 0.17677669529663687f; o.y *= 0.17677669529663687f; }
                    float* dst = (sel == 0 ? g_q : (sel == 1 ? g_k : g_v))
                                 + ((bb * NHEADS + h) * NTOK + nn) * HD + d;
                    *(float2*)dst = o;
                }
            }
        }
    }
}

// ---------------------------------------------------------------------------
// gemm1 (proj, R10 proven): A (g_att) through double-buffered smem; B frags
// direct LDG from g_fp. 256 threads, 8 warps 2x4, 2 CTAs/SM.
// ---------------------------------------------------------------------------
__global__ void __launch_bounds__(256, 2)
gemm1_hmma(const float* __restrict__ bias, float* __restrict__ out)
{
    extern __shared__ __align__(16) char dsmem[];
    const float* __restrict__ A = (const float*)g_att;

    const int tid = threadIdx.x;
    const int wid = tid >> 5;
    const int lid = tid & 31;
    const int m0  = blockIdx.y * 128;
    const int n0b = blockIdx.x * 128;
    const int warpM = (wid >> 2) * 64;
    const int warpN = (wid & 3) * 32;

    const uint32_t uS = smem_u32(dsmem);

    const int grow = tid >> 1;
    const int gkh  = (tid & 1) * 16;
    const float* Ag = A + (m0 + grow) * EMB + gkh;
    const int selem = grow * SPAD + gkh;
    const int tbase = (n0b >> 4) + (warpN >> 4);

    float acc[4][4][4];
#pragma unroll
    for (int i = 0; i < 4; i++)
#pragma unroll
        for (int j = 0; j < 4; j++)
#pragma unroll
            for (int r = 0; r < 4; r++) acc[i][j][r] = 0.f;

    const int aRow = warpM + (lid & 15);
    const int aCol = (lid >> 4) << 3;

#pragma unroll
    for (int c = 0; c < 8; ++c) {
        __nv_bfloat16* tb = (__nv_bfloat16*)(dsmem + (c & 1) * BUF_BYTES);
        {
            const int ko = c * 32;
            const float4 va0 = *(const float4*)(Ag + ko);
            const float4 va1 = *(const float4*)(Ag + ko + 4);
            const float4 va2 = *(const float4*)(Ag + ko + 8);
            const float4 va3 = *(const float4*)(Ag + ko + 12);
            const float fa[16] = {va0.x,va0.y,va0.z,va0.w, va1.x,va1.y,va1.z,va1.w,
                                  va2.x,va2.y,va2.z,va2.w, va3.x,va3.y,va3.z,va3.w};
            uint32_t ah[8], al[8];
#pragma unroll
            for (int e = 0; e < 8; ++e)
                split2(fa[2*e], fa[2*e+1], ah[e], al[e]);
            __nv_bfloat16* sa_h = tb + selem;
            ((uint4*)sa_h)[0] = make_uint4(ah[0],ah[1],ah[2],ah[3]);
            ((uint4*)sa_h)[1] = make_uint4(ah[4],ah[5],ah[6],ah[7]);
            __nv_bfloat16* sa_l = (__nv_bfloat16*)((char*)tb + OFF_ALO) + selem;
            ((uint4*)sa_l)[0] = make_uint4(al[0],al[1],al[2],al[3]);
            ((uint4*)sa_l)[1] = make_uint4(al[4],al[5],al[6],al[7]);
        }
        __syncthreads();

        const uint32_t uAhi = uS + (c & 1) * BUF_BYTES;
        const uint32_t uAlo = uAhi + OFF_ALO;

#pragma unroll
        for (int kk = 0; kk < 32; kk += 16) {
            const int ks = c * 2 + (kk >> 4);
            const uint4 bh0 = g_fp[(((tbase + 0)*16 + ks)*2 + 0)*32 + lid];
            const uint4 bh1 = g_fp[(((tbase + 1)*16 + ks)*2 + 0)*32 + lid];
            const uint4 bl0 = g_fp[(((tbase + 0)*16 + ks)*2 + 1)*32 + lid];
            const uint4 bl1 = g_fp[(((tbase + 1)*16 + ks)*2 + 1)*32 + lid];
            const uint32_t bhi[4][2] = {{bh0.x,bh0.y},{bh0.z,bh0.w},
                                        {bh1.x,bh1.y},{bh1.z,bh1.w}};
            const uint32_t blo[4][2] = {{bl0.x,bl0.y},{bl0.z,bl0.w},
                                        {bl1.x,bl1.y},{bl1.z,bl1.w}};

            uint32_t ahi[4][4], alo[4][4];
#pragma unroll
            for (int i = 0; i < 4; ++i) {
                const uint32_t off = (uint32_t)(((aRow + i*16) * SPAD + kk + aCol) * 2);
                ldm_x4(ahi[i][0], ahi[i][1], ahi[i][2], ahi[i][3], uAhi + off);
                ldm_x4(alo[i][0], alo[i][1], alo[i][2], alo[i][3], uAlo + off);
            }
#pragma unroll
            for (int i = 0; i < 4; ++i)
#pragma unroll
                for (int j = 0; j < 4; ++j) {
                    mma_bf16(acc[i][j], ahi[i][0],ahi[i][1],ahi[i][2],ahi[i][3],
                             bhi[j][0], bhi[j][1]);
                    mma_bf16(acc[i][j], ahi[i][0],ahi[i][1],ahi[i][2],ahi[i][3],
                             blo[j][0], blo[j][1]);
                    mma_bf16(acc[i][j], alo[i][0],alo[i][1],alo[i][2],alo[i][3],
                             bhi[j][0], bhi[j][1]);
                }
        }
    }

#pragma unroll
    for (int i = 0; i < 4; ++i) {
#pragma unroll
        for (int j = 0; j < 4; ++j) {
            const int n = n0b + warpN + j * 8 + 2 * (lid & 3);
            const float b0 = bias[n], b1 = bias[n + 1];
#pragma unroll
            for (int half = 0; half < 2; ++half) {
                const int m = m0 + warpM + i * 16 + (lid >> 2) + half * 8;
                float2 o;
                o.x = acc[i][j][half*2+0] + b0;
                o.y = acc[i][j][half*2+1] + b1;
                *(float2*)(out + m * EMB + n) = o;
            }
        }
    }
}

// ---------------------------------------------------------------------------
// Combined mask + rel-pos bias: [64*8][49][64]; padding cols (j>=49) = -1e9
// ---------------------------------------------------------------------------
__global__ void __launch_bounds__(256)
cmb_kernel(const float* __restrict__ mask, const float* __restrict__ bias_table)
{
    const int wh = blockIdx.x;
    const int w  = wh >> 3;
    const int h  = wh & 7;
    for (int e = threadIdx.x; e < NTOK * 64; e += 256) {
        const int q = e >> 6;
        const int j = e & 63;
        float v = -1e9f;
        if (j < NTOK) {
            const int qi = q / 7, qj = q - (q / 7) * 7;
            const int ki = j / 7, kj = j - (j / 7) * 7;
            const int idx = (qi - ki + 6) * 13 + (qj - kj + 6);
            v = mask[(w * NTOK + q) * NTOK + j] + bias_table[idx * NHEADS + h];
        }
        g_cmb[(wh * NTOK + q) * 64 + j] = v;
    }
}

// ---------------------------------------------------------------------------
// HMMA attention (R13 proven): block = ONE head, 128 threads, 4 warps,
// warp = (q-half, quadrant).
// ---------------------------------------------------------------------------
__global__ void __launch_bounds__(128)
attn_hmma()
{
    extern __shared__ __align__(16) char dsm[];
    const int tid  = threadIdx.x;
    const int wid  = tid >> 5;
    const int lane = tid & 31;
    const int half = wid >> 1;
    const int i2   = wid & 1;
    const int b    = blockIdx.x >> 3;
    const int h    = blockIdx.x & 7;
    const int bh   = blockIdx.x;

    __nv_bfloat16* skh = (__nv_bfloat16*)(dsm);
    __nv_bfloat16* skl = (__nv_bfloat16*)(dsm + 5120);
    __nv_bfloat16* svh = (__nv_bfloat16*)(dsm + 10240);
    __nv_bfloat16* svl = (__nv_bfloat16*)(dsm + 15360);

    const float* gK = g_k + bh * (NTOK * HD);
    const float* gV = g_v + bh * (NTOK * HD);
    for (int e = tid; e < 392; e += 128) {
        const int row = e >> 3, cg = (e & 7) << 2;
        const float4 kv = *(const float4*)(gK + row * 32 + cg);
        uint32_t h0, l0, h1, l1;
        split2(kv.x, kv.y, h0, l0); split2(kv.z, kv.w, h1, l1);
        *(uint2*)(skh + row * SPAD + cg) = make_uint2(h0, h1);
        *(uint2*)(skl + row * SPAD + cg) = make_uint2(l0, l1);
        const float4 vv = *(const float4*)(gV + row * 32 + cg);
        split2(vv.x, vv.y, h0, l0); split2(vv.z, vv.w, h1, l1);
        *(uint2*)(svh + row * SPAD + cg) = make_uint2(h0, h1);
        *(uint2*)(svl + row * SPAD + cg) = make_uint2(l0, l1);
    }
    for (int e = tid; e < 300; e += 128) {
        const int row = 49 + e / 20, c = (e % 20) * 2;
        *(uint32_t*)(skh + row * SPAD + c) = 0;
        *(uint32_t*)(skl + row * SPAD + c) = 0;
        *(uint32_t*)(svh + row * SPAD + c) = 0;
        *(uint32_t*)(svl + row * SPAD + c) = 0;
    }
    __syncthreads();

    const uint32_t uKh = smem_u32(skh), uKl = smem_u32(skl);
    const uint32_t uVh = smem_u32(svh), uVl = smem_u32(svl);
    const int lr = lane >> 2, lc = lane & 3;
    const int bRowOff = ((lane >> 4) << 3) + (lane & 7);
    const int bColOff = ((lane >> 3) & 1) << 3;
    const int vRowOff = (lane & 7) + (((lane >> 3) & 1) << 3);
    const int vColOff = (lane >> 4) << 3;

    const float* gQ = g_q + bh * (NTOK * HD);
    const float* cb = g_cmb + ((((b & 63) * NHEADS + h) * NTOK) << 6);

    const int r0 = half * 32 + i2 * 16 + lr;
    const int ra = (r0 < 48) ? r0 : 48;
    const int rb = (r0 + 8 < 48) ? r0 + 8 : 48;

    uint32_t qh[2][4], ql[2][4];
#pragma unroll
    for (int kc = 0; kc < 2; ++kc) {
        const int k0 = kc * 16 + lc * 2;
        const float2 x0 = *(const float2*)(gQ + ra * 32 + k0);
        const float2 x1 = *(const float2*)(gQ + rb * 32 + k0);
        const float2 x2 = *(const float2*)(gQ + ra * 32 + k0 + 8);
        const float2 x3 = *(const float2*)(gQ + rb * 32 + k0 + 8);
        split2(x0.x, x0.y, qh[kc][0], ql[kc][0]);
        split2(x1.x, x1.y, qh[kc][1], ql[kc][1]);
        split2(x2.x, x2.y, qh[kc][2], ql[kc][2]);
        split2(x3.x, x3.y, qh[kc][3], ql[kc][3]);
    }

    float s[7][4];
#pragma unroll
    for (int t = 0; t < 7; ++t) {
        const float2 u = *(const float2*)(cb + (ra << 6) + t * 8 + lc * 2);
        const float2 v = *(const float2*)(cb + (rb << 6) + t * 8 + lc * 2);
        s[t][0] = u.x; s[t][1] = u.y;
        s[t][2] = v.x; s[t][3] = v.y;
    }

#pragma unroll
    for (int kc = 0; kc < 2; ++kc) {
        uint32_t kbh[8][2], kbl[8][2];
#pragma unroll
        for (int p = 0; p < 4; ++p) {
            const uint32_t off = (uint32_t)(((p*16 + bRowOff) * SPAD + kc*16 + bColOff) * 2);
            uint32_t r0_, r1_, r2_, r3_;
            ldm_x4(r0_, r1_, r2_, r3_, uKh + off);
            kbh[p*2][0] = r0_; kbh[p*2][1] = r1_; kbh[p*2+1][0] = r2_; kbh[p*2+1][1] = r3_;
            ldm_x4(r0_, r1_, r2_, r3_, uKl + off);
            kbl[p*2][0] = r0_; kbl[p*2][1] = r1_; kbl[p*2+1][0] = r2_; kbl[p*2+1][1] = r3_;
        }
#pragma unroll
        for (int t = 0; t < 7; ++t) {
            mma_bf16(s[t], qh[kc][0], qh[kc][1], qh[kc][2], qh[kc][3],
                     kbh[t][0], kbh[t][1]);
            mma_bf16(s[t], qh[kc][0], qh[kc][1], qh[kc][2], qh[kc][3],
                     kbl[t][0], kbl[t][1]);
            mma_bf16(s[t], ql[kc][0], ql[kc][1], ql[kc][2], ql[kc][3],
                     kbh[t][0], kbh[t][1]);
        }
    }

    float s0 = 0.f, s1 = 0.f;
#pragma unroll
    for (int t = 0; t < 7; ++t) {
        s[t][0] = __expf(s[t][0]);
        s[t][1] = __expf(s[t][1]);
        s[t][2] = __expf(s[t][2]);
        s[t][3] = __expf(s[t][3]);
        s0 += s[t][0] + s[t][1];
        s1 += s[t][2] + s[t][3];
    }
    s0 += __shfl_xor_sync(0xffffffffu, s0, 1);
    s0 += __shfl_xor_sync(0xffffffffu, s0, 2);
    s1 += __shfl_xor_sync(0xffffffffu, s1, 1);
    s1 += __shfl_xor_sync(0xffffffffu, s1, 2);
    const float inv0 = 1.f / s0;
    const float inv1 = 1.f / s1;

    float o[4][4];
#pragma unroll
    for (int dt = 0; dt < 4; ++dt)
#pragma unroll
        for (int r = 0; r < 4; ++r) o[dt][r] = 0.f;

#pragma unroll
    for (int kc = 0; kc < 4; ++kc) {
        uint32_t ph_[4], pl_[4];
        const int t0 = kc * 2, t1 = kc * 2 + 1;
        split2(s[t0][0], s[t0][1], ph_[0], pl_[0]);
        split2(s[t0][2], s[t0][3], ph_[1], pl_[1]);
        if (t1 < 7) {
            split2(s[t1][0], s[t1][1], ph_[2], pl_[2]);
            split2(s[t1][2], s[t1][3], ph_[3], pl_[3]);
        } else {
            ph_[2] = ph_[3] = pl_[2] = pl_[3] = 0u;
        }

        uint32_t vh_[4][2], vl_[4][2];
#pragma unroll
        for (int dp = 0; dp < 2; ++dp) {
            const uint32_t off = (uint32_t)(((kc*16 + vRowOff) * SPAD + dp*16 + vColOff) * 2);
            uint32_t r0_, r1_, r2_, r3_;
            ldm_x4_t(r0_, r1_, r2_, r3_, uVh + off);
            vh_[dp*2][0] = r0_; vh_[dp*2][1] = r1_; vh_[dp*2+1][0] = r2_; vh_[dp*2+1][1] = r3_;
            ldm_x4_t(r0_, r1_, r2_, r3_, uVl + off);
            vl_[dp*2][0] = r0_; vl_[dp*2][1] = r1_; vl_[dp*2+1][0] = r2_; vl_[dp*2+1][1] = r3_;
        }
#pragma unroll
        for (int dt = 0; dt < 4; ++dt) {
            mma_bf16(o[dt], ph_[0], ph_[1], ph_[2], ph_[3], vh_[dt][0], vh_[dt][1]);
            mma_bf16(o[dt], pl_[0], pl_[1], pl_[2], pl_[3], vh_[dt][0], vh_[dt][1]);
            mma_bf16(o[dt], ph_[0], ph_[1], ph_[2], ph_[3], vl_[dt][0], vl_[dt][1]);
        }
    }

#pragma unroll
    for (int dt = 0; dt < 4; ++dt) {
        const int d = dt * 8 + lc * 2;
        if (r0 < NTOK) {
            float2 o2;
            o2.x = o[dt][0] * inv0;
            o2.y = o[dt][1] * inv0;
            *(float2*)(g_att + (b * NTOK + r0) * EMB + h * 32 + d) = o2;
        }
        if (r0 + 8 < NTOK) {
            float2 o2;
            o2.x = o[dt][2] * inv1;
            o2.y = o[dt][3] * inv1;
            *(float2*)(g_att + (b * NTOK + r0 + 8) * EMB + h * 32 + d) = o2;
        }
    }
}

// ---------------------------------------------------------------------------
extern "C" void kernel_launch(void* const* d_in, const int* in_sizes, int n_in,
                              void* d_out, int out_size)
{
    const float* x          = (const float*)d_in[0];
    const float* mask       = (const float*)d_in[1];
    const float* qkv_w      = (const float*)d_in[2];
    const float* qkv_b      = (const float*)d_in[3];
    const float* proj_w     = (const float*)d_in[4];
    const float* proj_b     = (const float*)d_in[5];
    const float* bias_table = (const float*)d_in[6];
    float* out = (float*)d_out;

    uint4* fq = nullptr; uint4* fp = nullptr;
    cudaGetSymbolAddress((void**)&fq, g_fq);
    cudaGetSymbolAddress((void**)&fp, g_fp);

    cudaFuncSetAttribute(gemm1_hmma, cudaFuncAttributeMaxDynamicSharedMemorySize, SMEM_BYTES);
    cudaFuncSetAttribute(attn_hmma,  cudaFuncAttributeMaxDynamicSharedMemorySize, ATTN_SMEM);

    cmb_kernel<<<64 * NHEADS, 256>>>(mask, bias_table);
    prep_w<<<48, 256>>>(qkv_w, fq);
    prep_w<<<16, 256>>>(proj_w, fp);
    prep_x<<<MTILES, 256>>>(x);
    gemm0_frag<<<dim3(768 / 96, (MROWS + 95) / 96), 128>>>(qkv_b);
    attn_hmma<<<BQ * NHEADS, 128, ATTN_SMEM>>>();
    gemm1_hmma<<<dim3(EMB / 128, MROWS / 128), 256, SMEM_BYTES>>>(proj_b, out);
}

// round 16
// speedup vs baseline: 1.1329x; 1.1329x over previous
#include <cuda_runtime.h>
#include <cuda_bf16.h>
#include <cstdint>

#define BQ 4096
#define NTOK 49
#define EMB 256
#define NHEADS 8
#define HD 32
#define MROWS (BQ*NTOK)   // 200704 = 128*1568
#define MTILES (MROWS/16) // 12544
#define SPAD 40           // bf16 row stride: conflict-free ldmatrix

// gemm1 smem: A hi/lo, double buffered
#define OFF_ALO 10240
#define BUF_BYTES 20480
#define SMEM_BYTES (2*BUF_BYTES)   // 40960

// attention smem: ONE head: Khi,Klo,Vhi,Vlo tiles of 64x40 bf16 (5120 B each)
#define ATTN_SMEM 20480

// Scratch (device globals: allocation-free), 16B aligned
__device__ __align__(16) float g_q[BQ*NHEADS*NTOK*HD];
__device__ __align__(16) float g_k[BQ*NHEADS*NTOK*HD];
__device__ __align__(16) float g_v[BQ*NHEADS*NTOK*HD];
__device__ __align__(16) float g_att[MROWS*EMB];
__device__ __align__(16) float g_cmb[64*NHEADS*NTOK*64];  // mask+bias, pad = -1e9

// Pre-permuted fragments (per-lane ldmatrix.x4 output -> direct LDG.128)
__device__ uint4 g_fq[48*16*2*32];        // qkv_w B-frags (786 KB)
__device__ uint4 g_fp[16*16*2*32];        // proj_w B-frags (256 KB)
__device__ uint4 g_fx[MTILES*16*2*32];    // x A-frags (205 MB)

// ---------------------------------------------------------------------------
// PTX helpers
// ---------------------------------------------------------------------------
__device__ __forceinline__ uint32_t smem_u32(const void* p) {
    uint32_t a;
    asm("{ .reg .u64 t; cvta.to.shared.u64 t, %1; cvt.u32.u64 %0, t; }"
        : "=r"(a) : "l"(p));
    return a;
}

__device__ __forceinline__ void ldm_x4(uint32_t& r0, uint32_t& r1,
                                       uint32_t& r2, uint32_t& r3, uint32_t addr) {
    asm volatile("ldmatrix.sync.aligned.m8n8.x4.shared.b16 {%0,%1,%2,%3}, [%4];"
                 : "=r"(r0), "=r"(r1), "=r"(r2), "=r"(r3) : "r"(addr));
}

__device__ __forceinline__ void ldm_x4_t(uint32_t& r0, uint32_t& r1,
                                         uint32_t& r2, uint32_t& r3, uint32_t addr) {
    asm volatile("ldmatrix.sync.aligned.m8n8.x4.trans.shared.b16 {%0,%1,%2,%3}, [%4];"
                 : "=r"(r0), "=r"(r1), "=r"(r2), "=r"(r3) : "r"(addr));
}

__device__ __forceinline__ void mma_bf16(float* c, uint32_t a0, uint32_t a1,
                                         uint32_t a2, uint32_t a3,
                                         uint32_t b0, uint32_t b1) {
    asm volatile(
        "mma.sync.aligned.m16n8k16.row.col.f32.bf16.bf16.f32 "
        "{%0,%1,%2,%3}, {%4,%5,%6,%7}, {%8,%9}, {%0,%1,%2,%3};"
        : "+f"(c[0]), "+f"(c[1]), "+f"(c[2]), "+f"(c[3])
        : "r"(a0), "r"(a1), "r"(a2), "r"(a3), "r"(b0), "r"(b1));
}

__device__ __forceinline__ uint32_t pack_bf2(float a, float b) {
    __nv_bfloat162 v = __floats2bfloat162_rn(a, b);
    return *reinterpret_cast<uint32_t*>(&v);
}

__device__ __forceinline__ void split2(float x0, float x1, uint32_t& hi, uint32_t& lo) {
    hi = pack_bf2(x0, x1);
    const __nv_bfloat162 hv = *reinterpret_cast<const __nv_bfloat162*>(&hi);
    lo = pack_bf2(x0 - __bfloat162float(hv.x), x1 - __bfloat162float(hv.y));
}

// ---------------------------------------------------------------------------
// Merged small-prep kernel: 576 blocks.
//   blocks [0,512):   cmb = mask + rel-pos bias, [64*8][49][64], pad = -1e9
//   blocks [512,560): qkv_w B-frag prep (48 n16 tiles)
//   blocks [560,576): proj_w B-frag prep (16 n16 tiles)
// ---------------------------------------------------------------------------
__global__ void __launch_bounds__(256)
prep_all(const float* __restrict__ mask, const float* __restrict__ bias_table,
         const float* __restrict__ qkv_w, const float* __restrict__ proj_w,
         uint4* __restrict__ fq, uint4* __restrict__ fp)
{
    const int bid = blockIdx.x;
    if (bid < 512) {
        const int wh = bid;
        const int w  = wh >> 3;
        const int h  = wh & 7;
        for (int e = threadIdx.x; e < NTOK * 64; e += 256) {
            const int q = e >> 6;
            const int j = e & 63;
            float v = -1e9f;
            if (j < NTOK) {
                const int qi = q / 7, qj = q - (q / 7) * 7;
                const int ki = j / 7, kj = j - (j / 7) * 7;
                const int idx = (qi - ki + 6) * 13 + (qj - kj + 6);
                v = mask[(w * NTOK + q) * NTOK + j] + bias_table[idx * NHEADS + h];
            }
            g_cmb[(wh * NTOK + q) * 64 + j] = v;
        }
        return;
    }

    // ---- weight B-frag prep ----
    __shared__ __align__(16) __nv_bfloat16 ph[8][16*SPAD];
    __shared__ __align__(16) __nv_bfloat16 pl[8][16*SPAD];
    const float* W;
    uint4* outf;
    int t;
    if (bid < 560) { W = qkv_w;  outf = fq; t = bid - 512; }
    else           { W = proj_w; outf = fp; t = bid - 560; }

    const int wid  = threadIdx.x >> 5;
    const int lane = threadIdx.x & 31;
    const uint32_t uh = smem_u32(ph[wid]);
    const uint32_t ul = smem_u32(pl[wid]);
    const int row = lane >> 1, c8 = (lane & 1) * 8;

#pragma unroll
    for (int pass = 0; pass < 2; ++pass) {
        const int ks = wid + pass * 8;
        const float* p = W + (t*16 + row) * EMB + ks*16 + c8;
        const float4 v0 = ((const float4*)p)[0];
        const float4 v1 = ((const float4*)p)[1];
        uint32_t h[4], l[4];
        split2(v0.x, v0.y, h[0], l[0]);
        split2(v0.z, v0.w, h[1], l[1]);
        split2(v1.x, v1.y, h[2], l[2]);
        split2(v1.z, v1.w, h[3], l[3]);
        __nv_bfloat16* dh = ph[wid] + row*SPAD + c8;
        ((uint2*)dh)[0] = make_uint2(h[0], h[1]);
        ((uint2*)dh)[1] = make_uint2(h[2], h[3]);
        __nv_bfloat16* dl = pl[wid] + row*SPAD + c8;
        ((uint2*)dl)[0] = make_uint2(l[0], l[1]);
        ((uint2*)dl)[1] = make_uint2(l[2], l[3]);
        __syncwarp();

        const uint32_t aoff = (uint32_t)(((((lane>>4)<<3) + (lane&7)) * SPAD
                                          + (((lane>>3)&1)<<3)) * 2);
        uint32_t r0, r1, r2, r3;
        ldm_x4(r0, r1, r2, r3, uh + aoff);
        outf[((t*16 + ks)*2 + 0)*32 + lane] = make_uint4(r0, r1, r2, r3);
        ldm_x4(r0, r1, r2, r3, ul + aoff);
        outf[((t*16 + ks)*2 + 1)*32 + lane] = make_uint4(r0, r1, r2, r3);
        __syncwarp();
    }
}

// ---------------------------------------------------------------------------
// x prep (A-operand fragments): block = one m16 tile, warp w -> ksteps w, w+8.
// A-operand lane addressing (rows = lane&15, col half = (lane>>4)*8).
// ---------------------------------------------------------------------------
__global__ void __launch_bounds__(256)
prep_x(const float* __restrict__ X)
{
    __shared__ __align__(16) __nv_bfloat16 ph[8][16*SPAD];
    __shared__ __align__(16) __nv_bfloat16 pl[8][16*SPAD];
    const int t    = blockIdx.x;
    const int wid  = threadIdx.x >> 5;
    const int lane = threadIdx.x & 31;
    const uint32_t uh = smem_u32(ph[wid]);
    const uint32_t ul = smem_u32(pl[wid]);
    const int row = lane >> 1, c8 = (lane & 1) * 8;

#pragma unroll
    for (int pass = 0; pass < 2; ++pass) {
        const int ks = wid + pass * 8;
        const float* p = X + (t*16 + row) * EMB + ks*16 + c8;
        const float4 v0 = ((const float4*)p)[0];
        const float4 v1 = ((const float4*)p)[1];
        uint32_t h[4], l[4];
        split2(v0.x, v0.y, h[0], l[0]);
        split2(v0.z, v0.w, h[1], l[1]);
        split2(v1.x, v1.y, h[2], l[2]);
        split2(v1.z, v1.w, h[3], l[3]);
        __nv_bfloat16* dh = ph[wid] + row*SPAD + c8;
        ((uint2*)dh)[0] = make_uint2(h[0], h[1]);
        ((uint2*)dh)[1] = make_uint2(h[2], h[3]);
        __nv_bfloat16* dl = pl[wid] + row*SPAD + c8;
        ((uint2*)dl)[0] = make_uint2(l[0], l[1]);
        ((uint2*)dl)[1] = make_uint2(l[2], l[3]);
        __syncwarp();

        const uint32_t aoff = (uint32_t)(((lane & 15) * SPAD + ((lane >> 4) << 3)) * 2);
        uint32_t r0, r1, r2, r3;
        ldm_x4(r0, r1, r2, r3, uh + aoff);
        g_fx[((t*16 + ks)*2 + 0)*32 + lane] = make_uint4(r0, r1, r2, r3);
        ldm_x4(r0, r1, r2, r3, ul + aoff);
        g_fx[((t*16 + ks)*2 + 1)*32 + lane] = make_uint4(r0, r1, r2, r3);
        __syncwarp();
    }
}

// ---------------------------------------------------------------------------
// gemm0 (QKV, R14 proven): fragment streaming, 128x96 CTA tile, 4 warps of
// 64x48. No smem, no syncs: A-frags from g_fx, B-frags from g_fq, 3-pass
// hi/lo, scatter epilogue. 3 CTAs/SM.
// ---------------------------------------------------------------------------
__global__ void __launch_bounds__(128, 3)
gemm0_frag(const float* __restrict__ bias)
{
    const int tid = threadIdx.x;
    const int wid = tid >> 5;
    const int lid = tid & 31;
    const int m0  = blockIdx.y * 128;
    const int n0  = blockIdx.x * 96 + (wid & 1) * 48;   // warp's first n col
    const int mt  = (m0 >> 4) + (wid >> 1) * 4;          // first of 4 m16 tiles
    const int nt  = n0 >> 4;                             // first of 3 n16 tiles

    float acc[4][6][4];
#pragma unroll
    for (int i = 0; i < 4; i++)
#pragma unroll
        for (int j = 0; j < 6; j++)
#pragma unroll
            for (int r = 0; r < 4; r++) acc[i][j][r] = 0.f;

    const uint4* __restrict__ Ax = g_fx + (size_t)mt * 1024 + lid;
    const uint4* __restrict__ Bx = g_fq + (size_t)nt * 1024 + lid;

#pragma unroll 4
    for (int ks = 0; ks < 16; ++ks) {
        uint4 fh[4], fl[4];
#pragma unroll
        for (int i = 0; i < 4; ++i) {
            fh[i] = Ax[(size_t)i * 1024 + ks * 64];
            fl[i] = Ax[(size_t)i * 1024 + ks * 64 + 32];
        }
#pragma unroll
        for (int jt = 0; jt < 3; ++jt) {
            const uint4 bh = Bx[(size_t)jt * 1024 + ks * 64];
            const uint4 bl = Bx[(size_t)jt * 1024 + ks * 64 + 32];
#pragma unroll
            for (int i = 0; i < 4; ++i) {
                mma_bf16(acc[i][2*jt+0], fh[i].x, fh[i].y, fh[i].z, fh[i].w, bh.x, bh.y);
                mma_bf16(acc[i][2*jt+1], fh[i].x, fh[i].y, fh[i].z, fh[i].w, bh.z, bh.w);
                mma_bf16(acc[i][2*jt+0], fh[i].x, fh[i].y, fh[i].z, fh[i].w, bl.x, bl.y);
                mma_bf16(acc[i][2*jt+1], fh[i].x, fh[i].y, fh[i].z, fh[i].w, bl.z, bl.w);
                mma_bf16(acc[i][2*jt+0], fl[i].x, fl[i].y, fl[i].z, fl[i].w, bh.x, bh.y);
                mma_bf16(acc[i][2*jt+1], fl[i].x, fl[i].y, fl[i].z, fl[i].w, bh.z, bh.w);
            }
        }
    }

    // ---- scatter epilogue: q/k/v (q scaled) ----
#pragma unroll
    for (int i = 0; i < 4; ++i) {
#pragma unroll
        for (int j = 0; j < 6; ++j) {
            const int n = n0 + j * 8 + 2 * (lid & 3);
            const float b0 = bias[n], b1 = bias[n + 1];
#pragma unroll
            for (int half = 0; half < 2; ++half) {
                const int m = m0 + (wid >> 1) * 64 + i * 16 + (lid >> 2) + half * 8;
                float2 o;
                o.x = acc[i][j][half*2+0] + b0;
                o.y = acc[i][j][half*2+1] + b1;
                const int bb  = m / NTOK;
                const int nn  = m - bb * NTOK;
                const int sel = n >> 8;
                const int h   = (n >> 5) & 7;
                const int d   = n & 31;
                if (sel == 0) { o.x *= 0.17677669529663687f; o.y *= 0.17677669529663687f; }
                float* dst = (sel == 0 ? g_q : (sel == 1 ? g_k : g_v))
                             + ((bb * NHEADS + h) * NTOK + nn) * HD + d;
                *(float2*)dst = o;
            }
        }
    }
}

// ---------------------------------------------------------------------------
// gemm1 (proj, R10 proven): A (g_att) through double-buffered smem; B frags
// direct LDG from g_fp. 256 threads, 8 warps 2x4, 2 CTAs/SM.
// ---------------------------------------------------------------------------
__global__ void __launch_bounds__(256, 2)
gemm1_hmma(const float* __restrict__ bias, float* __restrict__ out)
{
    extern __shared__ __align__(16) char dsmem[];
    const float* __restrict__ A = (const float*)g_att;

    const int tid = threadIdx.x;
    const int wid = tid >> 5;
    const int lid = tid & 31;
    const int m0  = blockIdx.y * 128;
    const int n0b = blockIdx.x * 128;
    const int warpM = (wid >> 2) * 64;
    const int warpN = (wid & 3) * 32;

    const uint32_t uS = smem_u32(dsmem);

    const int grow = tid >> 1;
    const int gkh  = (tid & 1) * 16;
    const float* Ag = A + (m0 + grow) * EMB + gkh;
    const int selem = grow * SPAD + gkh;
    const int tbase = (n0b >> 4) + (warpN >> 4);

    float acc[4][4][4];
#pragma unroll
    for (int i = 0; i < 4; i++)
#pragma unroll
        for (int j = 0; j < 4; j++)
#pragma unroll
            for (int r = 0; r < 4; r++) acc[i][j][r] = 0.f;

    const int aRow = warpM + (lid & 15);
    const int aCol = (lid >> 4) << 3;

#pragma unroll
    for (int c = 0; c < 8; ++c) {
        __nv_bfloat16* tb = (__nv_bfloat16*)(dsmem + (c & 1) * BUF_BYTES);
        {
            const int ko = c * 32;
            const float4 va0 = *(const float4*)(Ag + ko);
            const float4 va1 = *(const float4*)(Ag + ko + 4);
            const float4 va2 = *(const float4*)(Ag + ko + 8);
            const float4 va3 = *(const float4*)(Ag + ko + 12);
            const float fa[16] = {va0.x,va0.y,va0.z,va0.w, va1.x,va1.y,va1.z,va1.w,
                                  va2.x,va2.y,va2.z,va2.w, va3.x,va3.y,va3.z,va3.w};
            uint32_t ah[8], al[8];
#pragma unroll
            for (int e = 0; e < 8; ++e)
                split2(fa[2*e], fa[2*e+1], ah[e], al[e]);
            __nv_bfloat16* sa_h = tb + selem;
            ((uint4*)sa_h)[0] = make_uint4(ah[0],ah[1],ah[2],ah[3]);
            ((uint4*)sa_h)[1] = make_uint4(ah[4],ah[5],ah[6],ah[7]);
            __nv_bfloat16* sa_l = (__nv_bfloat16*)((char*)tb + OFF_ALO) + selem;
            ((uint4*)sa_l)[0] = make_uint4(al[0],al[1],al[2],al[3]);
            ((uint4*)sa_l)[1] = make_uint4(al[4],al[5],al[6],al[7]);
        }
        __syncthreads();

        const uint32_t uAhi = uS + (c & 1) * BUF_BYTES;
        const uint32_t uAlo = uAhi + OFF_ALO;

#pragma unroll
        for (int kk = 0; kk < 32; kk += 16) {
            const int ks = c * 2 + (kk >> 4);
            const uint4 bh0 = g_fp[(((tbase + 0)*16 + ks)*2 + 0)*32 + lid];
            const uint4 bh1 = g_fp[(((tbase + 1)*16 + ks)*2 + 0)*32 + lid];
            const uint4 bl0 = g_fp[(((tbase + 0)*16 + ks)*2 + 1)*32 + lid];
            const uint4 bl1 = g_fp[(((tbase + 1)*16 + ks)*2 + 1)*32 + lid];
            const uint32_t bhi[4][2] = {{bh0.x,bh0.y},{bh0.z,bh0.w},
                                        {bh1.x,bh1.y},{bh1.z,bh1.w}};
            const uint32_t blo[4][2] = {{bl0.x,bl0.y},{bl0.z,bl0.w},
                                        {bl1.x,bl1.y},{bl1.z,bl1.w}};

            uint32_t ahi[4][4], alo[4][4];
#pragma unroll
            for (int i = 0; i < 4; ++i) {
                const uint32_t off = (uint32_t)(((aRow + i*16) * SPAD + kk + aCol) * 2);
                ldm_x4(ahi[i][0], ahi[i][1], ahi[i][2], ahi[i][3], uAhi + off);
                ldm_x4(alo[i][0], alo[i][1], alo[i][2], alo[i][3], uAlo + off);
            }
#pragma unroll
            for (int i = 0; i < 4; ++i)
#pragma unroll
                for (int j = 0; j < 4; ++j) {
                    mma_bf16(acc[i][j], ahi[i][0],ahi[i][1],ahi[i][2],ahi[i][3],
                             bhi[j][0], bhi[j][1]);
                    mma_bf16(acc[i][j], ahi[i][0],ahi[i][1],ahi[i][2],ahi[i][3],
                             blo[j][0], blo[j][1]);
                    mma_bf16(acc[i][j], alo[i][0],alo[i][1],alo[i][2],alo[i][3],
                             bhi[j][0], bhi[j][1]);
                }
        }
    }

#pragma unroll
    for (int i = 0; i < 4; ++i) {
#pragma unroll
        for (int j = 0; j < 4; ++j) {
            const int n = n0b + warpN + j * 8 + 2 * (lid & 3);
            const float b0 = bias[n], b1 = bias[n + 1];
#pragma unroll
            for (int half = 0; half < 2; ++half) {
                const int m = m0 + warpM + i * 16 + (lid >> 2) + half * 8;
                float2 o;
                o.x = acc[i][j][half*2+0] + b0;
                o.y = acc[i][j][half*2+1] + b1;
                *(float2*)(out + m * EMB + n) = o;
            }
        }
    }
}

// ---------------------------------------------------------------------------
// HMMA attention (R13 proven): block = ONE head, 128 threads, 4 warps,
// warp = (q-half, quadrant).
// ---------------------------------------------------------------------------
__global__ void __launch_bounds__(128)
attn_hmma()
{
    extern __shared__ __align__(16) char dsm[];
    const int tid  = threadIdx.x;
    const int wid  = tid >> 5;
    const int lane = tid & 31;
    const int half = wid >> 1;
    const int i2   = wid & 1;
    const int b    = blockIdx.x >> 3;
    const int h    = blockIdx.x & 7;
    const int bh   = blockIdx.x;

    __nv_bfloat16* skh = (__nv_bfloat16*)(dsm);
    __nv_bfloat16* skl = (__nv_bfloat16*)(dsm + 5120);
    __nv_bfloat16* svh = (__nv_bfloat16*)(dsm + 10240);
    __nv_bfloat16* svl = (__nv_bfloat16*)(dsm + 15360);

    const float* gK = g_k + bh * (NTOK * HD);
    const float* gV = g_v + bh * (NTOK * HD);
    for (int e = tid; e < 392; e += 128) {
        const int row = e >> 3, cg = (e & 7) << 2;
        const float4 kv = *(const float4*)(gK + row * 32 + cg);
        uint32_t h0, l0, h1, l1;
        split2(kv.x, kv.y, h0, l0); split2(kv.z, kv.w, h1, l1);
        *(uint2*)(skh + row * SPAD + cg) = make_uint2(h0, h1);
        *(uint2*)(skl + row * SPAD + cg) = make_uint2(l0, l1);
        const float4 vv = *(const float4*)(gV + row * 32 + cg);
        split2(vv.x, vv.y, h0, l0); split2(vv.z, vv.w, h1, l1);
        *(uint2*)(svh + row * SPAD + cg) = make_uint2(h0, h1);
        *(uint2*)(svl + row * SPAD + cg) = make_uint2(l0, l1);
    }
    for (int e = tid; e < 300; e += 128) {
        const int row = 49 + e / 20, c = (e % 20) * 2;
        *(uint32_t*)(skh + row * SPAD + c) = 0;
        *(uint32_t*)(skl + row * SPAD + c) = 0;
        *(uint32_t*)(svh + row * SPAD + c) = 0;
        *(uint32_t*)(svl + row * SPAD + c) = 0;
    }
    __syncthreads();

    const uint32_t uKh = smem_u32(skh), uKl = smem_u32(skl);
    const uint32_t uVh = smem_u32(svh), uVl = smem_u32(svl);
    const int lr = lane >> 2, lc = lane & 3;
    const int bRowOff = ((lane >> 4) << 3) + (lane & 7);
    const int bColOff = ((lane >> 3) & 1) << 3;
    const int vRowOff = (lane & 7) + (((lane >> 3) & 1) << 3);
    const int vColOff = (lane >> 4) << 3;

    const float* gQ = g_q + bh * (NTOK * HD);
    const float* cb = g_cmb + ((((b & 63) * NHEADS + h) * NTOK) << 6);

    const int r0 = half * 32 + i2 * 16 + lr;
    const int ra = (r0 < 48) ? r0 : 48;
    const int rb = (r0 + 8 < 48) ? r0 + 8 : 48;

    uint32_t qh[2][4], ql[2][4];
#pragma unroll
    for (int kc = 0; kc < 2; ++kc) {
        const int k0 = kc * 16 + lc * 2;
        const float2 x0 = *(const float2*)(gQ + ra * 32 + k0);
        const float2 x1 = *(const float2*)(gQ + rb * 32 + k0);
        const float2 x2 = *(const float2*)(gQ + ra * 32 + k0 + 8);
        const float2 x3 = *(const float2*)(gQ + rb * 32 + k0 + 8);
        split2(x0.x, x0.y, qh[kc][0], ql[kc][0]);
        split2(x1.x, x1.y, qh[kc][1], ql[kc][1]);
        split2(x2.x, x2.y, qh[kc][2], ql[kc][2]);
        split2(x3.x, x3.y, qh[kc][3], ql[kc][3]);
    }

    float s[7][4];
#pragma unroll
    for (int t = 0; t < 7; ++t) {
        const float2 u = *(const float2*)(cb + (ra << 6) + t * 8 + lc * 2);
        const float2 v = *(const float2*)(cb + (rb << 6) + t * 8 + lc * 2);
        s[t][0] = u.x; s[t][1] = u.y;
        s[t][2] = v.x; s[t][3] = v.y;
    }

#pragma unroll
    for (int kc = 0; kc < 2; ++kc) {
        uint32_t kbh[8][2], kbl[8][2];
#pragma unroll
        for (int p = 0; p < 4; ++p) {
            const uint32_t off = (uint32_t)(((p*16 + bRowOff) * SPAD + kc*16 + bColOff) * 2);
            uint32_t r0_, r1_, r2_, r3_;
            ldm_x4(r0_, r1_, r2_, r3_, uKh + off);
            kbh[p*2][0] = r0_; kbh[p*2][1] = r1_; kbh[p*2+1][0] = r2_; kbh[p*2+1][1] = r3_;
            ldm_x4(r0_, r1_, r2_, r3_, uKl + off);
            kbl[p*2][0] = r0_; kbl[p*2][1] = r1_; kbl[p*2+1][0] = r2_; kbl[p*2+1][1] = r3_;
        }
#pragma unroll
        for (int t = 0; t < 7; ++t) {
            mma_bf16(s[t], qh[kc][0], qh[kc][1], qh[kc][2], qh[kc][3],
                     kbh[t][0], kbh[t][1]);
            mma_bf16(s[t], qh[kc][0], qh[kc][1], qh[kc][2], qh[kc][3],
                     kbl[t][0], kbl[t][1]);
            mma_bf16(s[t], ql[kc][0], ql[kc][1], ql[kc][2], ql[kc][3],
                     kbh[t][0], kbh[t][1]);
        }
    }

    float s0 = 0.f, s1 = 0.f;
#pragma unroll
    for (int t = 0; t < 7; ++t) {
        s[t][0] = __expf(s[t][0]);
        s[t][1] = __expf(s[t][1]);
        s[t][2] = __expf(s[t][2]);
        s[t][3] = __expf(s[t][3]);
        s0 += s[t][0] + s[t][1];
        s1 += s[t][2] + s[t][3];
    }
    s0 += __shfl_xor_sync(0xffffffffu, s0, 1);
    s0 += __shfl_xor_sync(0xffffffffu, s0, 2);
    s1 += __shfl_xor_sync(0xffffffffu, s1, 1);
    s1 += __shfl_xor_sync(0xffffffffu, s1, 2);
    const float inv0 = 1.f / s0;
    const float inv1 = 1.f / s1;

    float o[4][4];
#pragma unroll
    for (int dt = 0; dt < 4; ++dt)
#pragma unroll
        for (int r = 0; r < 4; ++r) o[dt][r] = 0.f;

#pragma unroll
    for (int kc = 0; kc < 4; ++kc) {
        uint32_t ph_[4], pl_[4];
        const int t0 = kc * 2, t1 = kc * 2 + 1;
        split2(s[t0][0], s[t0][1], ph_[0], pl_[0]);
        split2(s[t0][2], s[t0][3], ph_[1], pl_[1]);
        if (t1 < 7) {
            split2(s[t1][0], s[t1][1], ph_[2], pl_[2]);
            split2(s[t1][2], s[t1][3], ph_[3], pl_[3]);
        } else {
            ph_[2] = ph_[3] = pl_[2] = pl_[3] = 0u;
        }

        uint32_t vh_[4][2], vl_[4][2];
#pragma unroll
        for (int dp = 0; dp < 2; ++dp) {
            const uint32_t off = (uint32_t)(((kc*16 + vRowOff) * SPAD + dp*16 + vColOff) * 2);
            uint32_t r0_, r1_, r2_, r3_;
            ldm_x4_t(r0_, r1_, r2_, r3_, uVh + off);
            vh_[dp*2][0] = r0_; vh_[dp*2][1] = r1_; vh_[dp*2+1][0] = r2_; vh_[dp*2+1][1] = r3_;
            ldm_x4_t(r0_, r1_, r2_, r3_, uVl + off);
            vl_[dp*2][0] = r0_; vl_[dp*2][1] = r1_; vl_[dp*2+1][0] = r2_; vl_[dp*2+1][1] = r3_;
        }
#pragma unroll
        for (int dt = 0; dt < 4; ++dt) {
            mma_bf16(o[dt], ph_[0], ph_[1], ph_[2], ph_[3], vh_[dt][0], vh_[dt][1]);
            mma_bf16(o[dt], pl_[0], pl_[1], pl_[2], pl_[3], vh_[dt][0], vh_[dt][1]);
            mma_bf16(o[dt], ph_[0], ph_[1], ph_[2], ph_[3], vl_[dt][0], vl_[dt][1]);
        }
    }

#pragma unroll
    for (int dt = 0; dt < 4; ++dt) {
        const int d = dt * 8 + lc * 2;
        if (r0 < NTOK) {
            float2 o2;
            o2.x = o[dt][0] * inv0;
            o2.y = o[dt][1] * inv0;
            *(float2*)(g_att + (b * NTOK + r0) * EMB + h * 32 + d) = o2;
        }
        if (r0 + 8 < NTOK) {
            float2 o2;
            o2.x = o[dt][2] * inv1;
            o2.y = o[dt][3] * inv1;
            *(float2*)(g_att + (b * NTOK + r0 + 8) * EMB + h * 32 + d) = o2;
        }
    }
}

// ---------------------------------------------------------------------------
extern "C" void kernel_launch(void* const* d_in, const int* in_sizes, int n_in,
                              void* d_out, int out_size)
{
    const float* x          = (const float*)d_in[0];
    const float* mask       = (const float*)d_in[1];
    const float* qkv_w      = (const float*)d_in[2];
    const float* qkv_b      = (const float*)d_in[3];
    const float* proj_w     = (const float*)d_in[4];
    const float* proj_b     = (const float*)d_in[5];
    const float* bias_table = (const float*)d_in[6];
    float* out = (float*)d_out;

    uint4* fq = nullptr; uint4* fp = nullptr;
    cudaGetSymbolAddress((void**)&fq, g_fq);
    cudaGetSymbolAddress((void**)&fp, g_fp);

    cudaFuncSetAttribute(gemm1_hmma, cudaFuncAttributeMaxDynamicSharedMemorySize, SMEM_BYTES);
    cudaFuncSetAttribute(attn_hmma,  cudaFuncAttributeMaxDynamicSharedMemorySize, ATTN_SMEM);

    prep_all<<<576, 256>>>(mask, bias_table, qkv_w, proj_w, fq, fp);
    prep_x<<<MTILES, 256>>>(x);
    gemm0_frag<<<dim3(768 / 96, MROWS / 128), 128>>>(qkv_b);
    attn_hmma<<<BQ * NHEADS, 128, ATTN_SMEM>>>();
    gemm1_hmma<<<dim3(EMB / 128, MROWS / 128), 256, SMEM_BYTES>>>(proj_b, out);
}

// round 17
// speedup vs baseline: 1.2293x; 1.0851x over previous
#include <cuda_runtime.h>
#include <cuda_bf16.h>
#include <cstdint>

#define BQ 4096
#define NTOK 49
#define EMB 256
#define NHEADS 8
#define HD 32
#define MROWS (BQ*NTOK)   // 200704 = 128*1568
#define MTILES (MROWS/16) // 12544
#define SPAD 40           // bf16 row stride: conflict-free ldmatrix

// gemm1 smem: A hi/lo, double buffered
#define OFF_ALO 10240
#define BUF_BYTES 20480
#define SMEM_BYTES (2*BUF_BYTES)   // 40960

// attention smem: ONE head: Khi,Klo,Vhi,Vlo tiles of 64x40 bf16 (5120 B each)
#define ATTN_SMEM 20480

#define SXF 260   // float staging stride: (4r+c) mod 32 distinct -> conflict-free gather

// Scratch (device globals: allocation-free), 16B aligned
__device__ __align__(16) float g_q[BQ*NHEADS*NTOK*HD];
__device__ __align__(16) float g_k[BQ*NHEADS*NTOK*HD];
__device__ __align__(16) float g_v[BQ*NHEADS*NTOK*HD];
__device__ __align__(16) float g_att[MROWS*EMB];
__device__ __align__(16) float g_cmb[64*NHEADS*NTOK*64];  // mask+bias, pad = -1e9

// Pre-permuted fragments (direct LDG.128 in the GEMMs)
__device__ uint4 g_fq[48*32*32];          // qkv_w tf32 B-frags (786 KB)
__device__ uint4 g_fp[16*16*2*32];        // proj_w bf16 B-frags (256 KB)
__device__ uint4 g_fx[MTILES*32*32];      // x tf32 A-frags (205 MB)

// ---------------------------------------------------------------------------
// PTX helpers
// ---------------------------------------------------------------------------
__device__ __forceinline__ uint32_t smem_u32(const void* p) {
    uint32_t a;
    asm("{ .reg .u64 t; cvta.to.shared.u64 t, %1; cvt.u32.u64 %0, t; }"
        : "=r"(a) : "l"(p));
    return a;
}

__device__ __forceinline__ void ldm_x4(uint32_t& r0, uint32_t& r1,
                                       uint32_t& r2, uint32_t& r3, uint32_t addr) {
    asm volatile("ldmatrix.sync.aligned.m8n8.x4.shared.b16 {%0,%1,%2,%3}, [%4];"
                 : "=r"(r0), "=r"(r1), "=r"(r2), "=r"(r3) : "r"(addr));
}

__device__ __forceinline__ void ldm_x4_t(uint32_t& r0, uint32_t& r1,
                                         uint32_t& r2, uint32_t& r3, uint32_t addr) {
    asm volatile("ldmatrix.sync.aligned.m8n8.x4.trans.shared.b16 {%0,%1,%2,%3}, [%4];"
                 : "=r"(r0), "=r"(r1), "=r"(r2), "=r"(r3) : "r"(addr));
}

__device__ __forceinline__ void mma_bf16(float* c, uint32_t a0, uint32_t a1,
                                         uint32_t a2, uint32_t a3,
                                         uint32_t b0, uint32_t b1) {
    asm volatile(
        "mma.sync.aligned.m16n8k16.row.col.f32.bf16.bf16.f32 "
        "{%0,%1,%2,%3}, {%4,%5,%6,%7}, {%8,%9}, {%0,%1,%2,%3};"
        : "+f"(c[0]), "+f"(c[1]), "+f"(c[2]), "+f"(c[3])
        : "r"(a0), "r"(a1), "r"(a2), "r"(a3), "r"(b0), "r"(b1));
}

__device__ __forceinline__ void mma_tf32(float* c, uint32_t a0, uint32_t a1,
                                         uint32_t a2, uint32_t a3,
                                         uint32_t b0, uint32_t b1) {
    asm volatile(
        "mma.sync.aligned.m16n8k8.row.col.f32.tf32.tf32.f32 "
        "{%0,%1,%2,%3}, {%4,%5,%6,%7}, {%8,%9}, {%0,%1,%2,%3};"
        : "+f"(c[0]), "+f"(c[1]), "+f"(c[2]), "+f"(c[3])
        : "r"(a0), "r"(a1), "r"(a2), "r"(a3), "r"(b0), "r"(b1));
}

__device__ __forceinline__ uint32_t f2tf32(float x) {
    uint32_t r;
    asm("cvt.rna.tf32.f32 %0, %1;" : "=r"(r) : "f"(x));
    return r;
}

__device__ __forceinline__ uint32_t pack_bf2(float a, float b) {
    __nv_bfloat162 v = __floats2bfloat162_rn(a, b);
    return *reinterpret_cast<uint32_t*>(&v);
}

__device__ __forceinline__ void split2(float x0, float x1, uint32_t& hi, uint32_t& lo) {
    hi = pack_bf2(x0, x1);
    const __nv_bfloat162 hv = *reinterpret_cast<const __nv_bfloat162*>(&hi);
    lo = pack_bf2(x0 - __bfloat162float(hv.x), x1 - __bfloat162float(hv.y));
}

// ---------------------------------------------------------------------------
// Merged prep kernel: 576 blocks.
//   [0,512):   cmb = mask + rel-pos bias, [64*8][49][64], pad = -1e9
//   [512,560): qkv_w tf32 B-frag prep (48 n16 tiles): per k8 step, per lane
//              uint4 {b0_lo, b1_lo, b0_hi, b1_hi} (two n8 halves), rna-cvt.
//   [560,576): proj_w bf16 B-frag prep (16 n16 tiles, unchanged hi/lo)
// ---------------------------------------------------------------------------
__global__ void __launch_bounds__(256)
prep_all(const float* __restrict__ mask, const float* __restrict__ bias_table,
         const float* __restrict__ qkv_w, const float* __restrict__ proj_w,
         uint4* __restrict__ fq, uint4* __restrict__ fp)
{
    const int bid = blockIdx.x;
    if (bid < 512) {
        const int wh = bid;
        const int w  = wh >> 3;
        const int h  = wh & 7;
        for (int e = threadIdx.x; e < NTOK * 64; e += 256) {
            const int q = e >> 6;
            const int j = e & 63;
            float v = -1e9f;
            if (j < NTOK) {
                const int qi = q / 7, qj = q - (q / 7) * 7;
                const int ki = j / 7, kj = j - (j / 7) * 7;
                const int idx = (qi - ki + 6) * 13 + (qj - kj + 6);
                v = mask[(w * NTOK + q) * NTOK + j] + bias_table[idx * NHEADS + h];
            }
            g_cmb[(wh * NTOK + q) * 64 + j] = v;
        }
        return;
    }

    const int wid  = threadIdx.x >> 5;
    const int lane = threadIdx.x & 31;

    if (bid < 560) {
        // ---- qkv_w -> tf32 B-frags ----
        __shared__ __align__(16) float sw[16 * SXF];
        const int t = bid - 512;
        for (int i = threadIdx.x; i < 1024; i += 256) {
            const int row = i >> 6, c4 = (i & 63) * 4;
            *(float4*)(sw + row * SXF + c4) =
                *(const float4*)(qkv_w + (t * 16 + row) * EMB + c4);
        }
        __syncthreads();
        const int r = lane >> 2, kc = lane & 3;
#pragma unroll
        for (int s = 0; s < 4; ++s) {
            const int ks8 = wid * 4 + s;
            const int c = ks8 * 8 + kc;
            uint4 o;
            o.x = f2tf32(sw[r * SXF + c]);            // b0, n8 lo
            o.y = f2tf32(sw[r * SXF + c + 4]);        // b1, n8 lo
            o.z = f2tf32(sw[(r + 8) * SXF + c]);      // b0, n8 hi
            o.w = f2tf32(sw[(r + 8) * SXF + c + 4]);  // b1, n8 hi
            fq[(t * 32 + ks8) * 32 + lane] = o;
        }
        return;
    }

    // ---- proj_w -> bf16 hi/lo B-frags (unchanged path for gemm1) ----
    __shared__ __align__(16) __nv_bfloat16 ph[8][16*SPAD];
    __shared__ __align__(16) __nv_bfloat16 pl[8][16*SPAD];
    const int t = bid - 560;
    const uint32_t uh = smem_u32(ph[wid]);
    const uint32_t ul = smem_u32(pl[wid]);
    const int row = lane >> 1, c8 = (lane & 1) * 8;

#pragma unroll
    for (int pass = 0; pass < 2; ++pass) {
        const int ks = wid + pass * 8;
        const float* p = proj_w + (t*16 + row) * EMB + ks*16 + c8;
        const float4 v0 = ((const float4*)p)[0];
        const float4 v1 = ((const float4*)p)[1];
        uint32_t h[4], l[4];
        split2(v0.x, v0.y, h[0], l[0]);
        split2(v0.z, v0.w, h[1], l[1]);
        split2(v1.x, v1.y, h[2], l[2]);
        split2(v1.z, v1.w, h[3], l[3]);
        __nv_bfloat16* dh = ph[wid] + row*SPAD + c8;
        ((uint2*)dh)[0] = make_uint2(h[0], h[1]);
        ((uint2*)dh)[1] = make_uint2(h[2], h[3]);
        __nv_bfloat16* dl = pl[wid] + row*SPAD + c8;
        ((uint2*)dl)[0] = make_uint2(l[0], l[1]);
        ((uint2*)dl)[1] = make_uint2(l[2], l[3]);
        __syncwarp();

        const uint32_t aoff = (uint32_t)(((((lane>>4)<<3) + (lane&7)) * SPAD
                                          + (((lane>>3)&1)<<3)) * 2);
        uint32_t r0, r1, r2, r3;
        ldm_x4(r0, r1, r2, r3, uh + aoff);
        fp[((t*16 + ks)*2 + 0)*32 + lane] = make_uint4(r0, r1, r2, r3);
        ldm_x4(r0, r1, r2, r3, ul + aoff);
        fp[((t*16 + ks)*2 + 1)*32 + lane] = make_uint4(r0, r1, r2, r3);
        __syncwarp();
    }
}

// ---------------------------------------------------------------------------
// x prep -> tf32 A-frags: block = one m16 tile; stage 16x256 to smem, then
// per lane gather {a0,a1,a2,a3} (m16n8k8 A layout), rna-cvt, STG.128.
// ---------------------------------------------------------------------------
__global__ void __launch_bounds__(256)
prep_x(const float* __restrict__ X)
{
    __shared__ __align__(16) float sx[16 * SXF];
    const int t    = blockIdx.x;
    const int wid  = threadIdx.x >> 5;
    const int lane = threadIdx.x & 31;

    for (int i = threadIdx.x; i < 1024; i += 256) {
        const int row = i >> 6, c4 = (i & 63) * 4;
        *(float4*)(sx + row * SXF + c4) =
            *(const float4*)(X + (t * 16 + row) * EMB + c4);
    }
    __syncthreads();

    const int r = lane >> 2, kc = lane & 3;
#pragma unroll
    for (int s = 0; s < 4; ++s) {
        const int ks8 = wid * 4 + s;
        const int c = ks8 * 8 + kc;
        uint4 o;
        o.x = f2tf32(sx[r * SXF + c]);            // a0
        o.y = f2tf32(sx[(r + 8) * SXF + c]);      // a1
        o.z = f2tf32(sx[r * SXF + c + 4]);        // a2
        o.w = f2tf32(sx[(r + 8) * SXF + c + 4]);  // a3
        g_fx[(t * 32 + ks8) * 32 + lane] = o;
    }
}

// ---------------------------------------------------------------------------
// gemm0 (QKV): single-pass tf32 fragment streaming, 128x96 CTA, 4 warps of
// 64x48. Per k8: 4 A + 3 B uint4 LDGs, 24 tf32 mma (2/3 the bf16-3pass mma
// cycles; identical frag bytes). No smem, no syncs, 3 CTAs/SM.
// ---------------------------------------------------------------------------
__global__ void __launch_bounds__(128, 3)
gemm0_frag(const float* __restrict__ bias)
{
    const int tid = threadIdx.x;
    const int wid = tid >> 5;
    const int lid = tid & 31;
    const int m0  = blockIdx.y * 128;
    const int n0  = blockIdx.x * 96 + (wid & 1) * 48;
    const int mt  = (m0 >> 4) + (wid >> 1) * 4;
    const int nt  = n0 >> 4;

    float acc[4][6][4];
#pragma unroll
    for (int i = 0; i < 4; i++)
#pragma unroll
        for (int j = 0; j < 6; j++)
#pragma unroll
            for (int r = 0; r < 4; r++) acc[i][j][r] = 0.f;

    const uint4* __restrict__ Ax = g_fx + (size_t)mt * 1024 + lid;
    const uint4* __restrict__ Bx = g_fq + (size_t)nt * 1024 + lid;

#pragma unroll 8
    for (int ks = 0; ks < 32; ++ks) {
        uint4 fa[4];
#pragma unroll
        for (int i = 0; i < 4; ++i)
            fa[i] = Ax[(size_t)i * 1024 + ks * 32];
#pragma unroll
        for (int jt = 0; jt < 3; ++jt) {
            const uint4 bb = Bx[(size_t)jt * 1024 + ks * 32];
#pragma unroll
            for (int i = 0; i < 4; ++i) {
                mma_tf32(acc[i][2*jt+0], fa[i].x, fa[i].y, fa[i].z, fa[i].w, bb.x, bb.y);
                mma_tf32(acc[i][2*jt+1], fa[i].x, fa[i].y, fa[i].z, fa[i].w, bb.z, bb.w);
            }
        }
    }

    // ---- scatter epilogue: q/k/v (q scaled) ----
#pragma unroll
    for (int i = 0; i < 4; ++i) {
#pragma unroll
        for (int j = 0; j < 6; ++j) {
            const int n = n0 + j * 8 + 2 * (lid & 3);
            const float b0 = bias[n], b1 = bias[n + 1];
#pragma unroll
            for (int half = 0; half < 2; ++half) {
                const int m = m0 + (wid >> 1) * 64 + i * 16 + (lid >> 2) + half * 8;
                float2 o;
                o.x = acc[i][j][half*2+0] + b0;
                o.y = acc[i][j][half*2+1] + b1;
                const int bb  = m / NTOK;
                const int nn  = m - bb * NTOK;
                const int sel = n >> 8;
                const int h   = (n >> 5) & 7;
                const int d   = n & 31;
                if (sel == 0) { o.x *= 0.17677669529663687f; o.y *= 0.17677669529663687f; }
                float* dst = (sel == 0 ? g_q : (sel == 1 ? g_k : g_v))
                             + ((bb * NHEADS + h) * NTOK + nn) * HD + d;
                *(float2*)dst = o;
            }
        }
    }
}

// ---------------------------------------------------------------------------
// gemm1 (proj, R10 proven): bf16 3-pass, A via double-buffered smem; B frags
// direct LDG from g_fp. 256 threads, 8 warps 2x4, 2 CTAs/SM.
// ---------------------------------------------------------------------------
__global__ void __launch_bounds__(256, 2)
gemm1_hmma(const float* __restrict__ bias, float* __restrict__ out)
{
    extern __shared__ __align__(16) char dsmem[];
    const float* __restrict__ A = (const float*)g_att;

    const int tid = threadIdx.x;
    const int wid = tid >> 5;
    const int lid = tid & 31;
    const int m0  = blockIdx.y * 128;
    const int n0b = blockIdx.x * 128;
    const int warpM = (wid >> 2) * 64;
    const int warpN = (wid & 3) * 32;

    const uint32_t uS = smem_u32(dsmem);

    const int grow = tid >> 1;
    const int gkh  = (tid & 1) * 16;
    const float* Ag = A + (m0 + grow) * EMB + gkh;
    const int selem = grow * SPAD + gkh;
    const int tbase = (n0b >> 4) + (warpN >> 4);

    float acc[4][4][4];
#pragma unroll
    for (int i = 0; i < 4; i++)
#pragma unroll
        for (int j = 0; j < 4; j++)
#pragma unroll
            for (int r = 0; r < 4; r++) acc[i][j][r] = 0.f;

    const int aRow = warpM + (lid & 15);
    const int aCol = (lid >> 4) << 3;

#pragma unroll
    for (int c = 0; c < 8; ++c) {
        __nv_bfloat16* tb = (__nv_bfloat16*)(dsmem + (c & 1) * BUF_BYTES);
        {
            const int ko = c * 32;
            const float4 va0 = *(const float4*)(Ag + ko);
            const float4 va1 = *(const float4*)(Ag + ko + 4);
            const float4 va2 = *(const float4*)(Ag + ko + 8);
            const float4 va3 = *(const float4*)(Ag + ko + 12);
            const float fa[16] = {va0.x,va0.y,va0.z,va0.w, va1.x,va1.y,va1.z,va1.w,
                                  va2.x,va2.y,va2.z,va2.w, va3.x,va3.y,va3.z,va3.w};
            uint32_t ah[8], al[8];
#pragma unroll
            for (int e = 0; e < 8; ++e)
                split2(fa[2*e], fa[2*e+1], ah[e], al[e]);
            __nv_bfloat16* sa_h = tb + selem;
            ((uint4*)sa_h)[0] = make_uint4(ah[0],ah[1],ah[2],ah[3]);
            ((uint4*)sa_h)[1] = make_uint4(ah[4],ah[5],ah[6],ah[7]);
            __nv_bfloat16* sa_l = (__nv_bfloat16*)((char*)tb + OFF_ALO) + selem;
            ((uint4*)sa_l)[0] = make_uint4(al[0],al[1],al[2],al[3]);
            ((uint4*)sa_l)[1] = make_uint4(al[4],al[5],al[6],al[7]);
        }
        __syncthreads();

        const uint32_t uAhi = uS + (c & 1) * BUF_BYTES;
        const uint32_t uAlo = uAhi + OFF_ALO;

#pragma unroll
        for (int kk = 0; kk < 32; kk += 16) {
            const int ks = c * 2 + (kk >> 4);
            const uint4 bh0 = g_fp[(((tbase + 0)*16 + ks)*2 + 0)*32 + lid];
            const uint4 bh1 = g_fp[(((tbase + 1)*16 + ks)*2 + 0)*32 + lid];
            const uint4 bl0 = g_fp[(((tbase + 0)*16 + ks)*2 + 1)*32 + lid];
            const uint4 bl1 = g_fp[(((tbase + 1)*16 + ks)*2 + 1)*32 + lid];
            const uint32_t bhi[4][2] = {{bh0.x,bh0.y},{bh0.z,bh0.w},
                                        {bh1.x,bh1.y},{bh1.z,bh1.w}};
            const uint32_t blo[4][2] = {{bl0.x,bl0.y},{bl0.z,bl0.w},
                                        {bl1.x,bl1.y},{bl1.z,bl1.w}};

            uint32_t ahi[4][4], alo[4][4];
#pragma unroll
            for (int i = 0; i < 4; ++i) {
                const uint32_t off = (uint32_t)(((aRow + i*16) * SPAD + kk + aCol) * 2);
                ldm_x4(ahi[i][0], ahi[i][1], ahi[i][2], ahi[i][3], uAhi + off);
                ldm_x4(alo[i][0], alo[i][1], alo[i][2], alo[i][3], uAlo + off);
            }
#pragma unroll
            for (int i = 0; i < 4; ++i)
#pragma unroll
                for (int j = 0; j < 4; ++j) {
                    mma_bf16(acc[i][j], ahi[i][0],ahi[i][1],ahi[i][2],ahi[i][3],
                             bhi[j][0], bhi[j][1]);
                    mma_bf16(acc[i][j], ahi[i][0],ahi[i][1],ahi[i][2],ahi[i][3],
                             blo[j][0], blo[j][1]);
                    mma_bf16(acc[i][j], alo[i][0],alo[i][1],alo[i][2],alo[i][3],
                             bhi[j][0], bhi[j][1]);
                }
        }
    }

#pragma unroll
    for (int i = 0; i < 4; ++i) {
#pragma unroll
        for (int j = 0; j < 4; ++j) {
            const int n = n0b + warpN + j * 8 + 2 * (lid & 3);
            const float b0 = bias[n], b1 = bias[n + 1];
#pragma unroll
            for (int half = 0; half < 2; ++half) {
                const int m = m0 + warpM + i * 16 + (lid >> 2) + half * 8;
                float2 o;
                o.x = acc[i][j][half*2+0] + b0;
                o.y = acc[i][j][half*2+1] + b1;
                *(float2*)(out + m * EMB + n) = o;
            }
        }
    }
}

// ---------------------------------------------------------------------------
// HMMA attention (R13 proven): block = ONE head, 128 threads, 4 warps,
// warp = (q-half, quadrant). bf16 3-pass.
// ---------------------------------------------------------------------------
__global__ void __launch_bounds__(128)
attn_hmma()
{
    extern __shared__ __align__(16) char dsm[];
    const int tid  = threadIdx.x;
    const int wid  = tid >> 5;
    const int lane = tid & 31;
    const int half = wid >> 1;
    const int i2   = wid & 1;
    const int b    = blockIdx.x >> 3;
    const int h    = blockIdx.x & 7;
    const int bh   = blockIdx.x;

    __nv_bfloat16* skh = (__nv_bfloat16*)(dsm);
    __nv_bfloat16* skl = (__nv_bfloat16*)(dsm + 5120);
    __nv_bfloat16* svh = (__nv_bfloat16*)(dsm + 10240);
    __nv_bfloat16* svl = (__nv_bfloat16*)(dsm + 15360);

    const float* gK = g_k + bh * (NTOK * HD);
    const float* gV = g_v + bh * (NTOK * HD);
    for (int e = tid; e < 392; e += 128) {
        const int row = e >> 3, cg = (e & 7) << 2;
        const float4 kv = *(const float4*)(gK + row * 32 + cg);
        uint32_t h0, l0, h1, l1;
        split2(kv.x, kv.y, h0, l0); split2(kv.z, kv.w, h1, l1);
        *(uint2*)(skh + row * SPAD + cg) = make_uint2(h0, h1);
        *(uint2*)(skl + row * SPAD + cg) = make_uint2(l0, l1);
        const float4 vv = *(const float4*)(gV + row * 32 + cg);
        split2(vv.x, vv.y, h0, l0); split2(vv.z, vv.w, h1, l1);
        *(uint2*)(svh + row * SPAD + cg) = make_uint2(h0, h1);
        *(uint2*)(svl + row * SPAD + cg) = make_uint2(l0, l1);
    }
    for (int e = tid; e < 300; e += 128) {
        const int row = 49 + e / 20, c = (e % 20) * 2;
        *(uint32_t*)(skh + row * SPAD + c) = 0;
        *(uint32_t*)(skl + row * SPAD + c) = 0;
        *(uint32_t*)(svh + row * SPAD + c) = 0;
        *(uint32_t*)(svl + row * SPAD + c) = 0;
    }
    __syncthreads();

    const uint32_t uKh = smem_u32(skh), uKl = smem_u32(skl);
    const uint32_t uVh = smem_u32(svh), uVl = smem_u32(svl);
    const int lr = lane >> 2, lc = lane & 3;
    const int bRowOff = ((lane >> 4) << 3) + (lane & 7);
    const int bColOff = ((lane >> 3) & 1) << 3;
    const int vRowOff = (lane & 7) + (((lane >> 3) & 1) << 3);
    const int vColOff = (lane >> 4) << 3;

    const float* gQ = g_q + bh * (NTOK * HD);
    const float* cb = g_cmb + ((((b & 63) * NHEADS + h) * NTOK) << 6);

    const int r0 = half * 32 + i2 * 16 + lr;
    const int ra = (r0 < 48) ? r0 : 48;
    const int rb = (r0 + 8 < 48) ? r0 + 8 : 48;

    uint32_t qh[2][4], ql[2][4];
#pragma unroll
    for (int kc = 0; kc < 2; ++kc) {
        const int k0 = kc * 16 + lc * 2;
        const float2 x0 = *(const float2*)(gQ + ra * 32 + k0);
        const float2 x1 = *(const float2*)(gQ + rb * 32 + k0);
        const float2 x2 = *(const float2*)(gQ + ra * 32 + k0 + 8);
        const float2 x3 = *(const float2*)(gQ + rb * 32 + k0 + 8);
        split2(x0.x, x0.y, qh[kc][0], ql[kc][0]);
        split2(x1.x, x1.y, qh[kc][1], ql[kc][1]);
        split2(x2.x, x2.y, qh[kc][2], ql[kc][2]);
        split2(x3.x, x3.y, qh[kc][3], ql[kc][3]);
    }

    float s[7][4];
#pragma unroll
    for (int t = 0; t < 7; ++t) {
        const float2 u = *(const float2*)(cb + (ra << 6) + t * 8 + lc * 2);
        const float2 v = *(const float2*)(cb + (rb << 6) + t * 8 + lc * 2);
        s[t][0] = u.x; s[t][1] = u.y;
        s[t][2] = v.x; s[t][3] = v.y;
    }

#pragma unroll
    for (int kc = 0; kc < 2; ++kc) {
        uint32_t kbh[8][2], kbl[8][2];
#pragma unroll
        for (int p = 0; p < 4; ++p) {
            const uint32_t off = (uint32_t)(((p*16 + bRowOff) * SPAD + kc*16 + bColOff) * 2);
            uint32_t r0_, r1_, r2_, r3_;
            ldm_x4(r0_, r1_, r2_, r3_, uKh + off);
            kbh[p*2][0] = r0_; kbh[p*2][1] = r1_; kbh[p*2+1][0] = r2_; kbh[p*2+1][1] = r3_;
            ldm_x4(r0_, r1_, r2_, r3_, uKl + off);
            kbl[p*2][0] = r0_; kbl[p*2][1] = r1_; kbl[p*2+1][0] = r2_; kbl[p*2+1][1] = r3_;
        }
#pragma unroll
        for (int t = 0; t < 7; ++t) {
            mma_bf16(s[t], qh[kc][0], qh[kc][1], qh[kc][2], qh[kc][3],
                     kbh[t][0], kbh[t][1]);
            mma_bf16(s[t], qh[kc][0], qh[kc][1], qh[kc][2], qh[kc][3],
                     kbl[t][0], kbl[t][1]);
            mma_bf16(s[t], ql[kc][0], ql[kc][1], ql[kc][2], ql[kc][3],
                     kbh[t][0], kbh[t][1]);
        }
    }

    float s0 = 0.f, s1 = 0.f;
#pragma unroll
    for (int t = 0; t < 7; ++t) {
        s[t][0] = __expf(s[t][0]);
        s[t][1] = __expf(s[t][1]);
        s[t][2] = __expf(s[t][2]);
        s[t][3] = __expf(s[t][3]);
        s0 += s[t][0] + s[t][1];
        s1 += s[t][2] + s[t][3];
    }
    s0 += __shfl_xor_sync(0xffffffffu, s0, 1);
    s0 += __shfl_xor_sync(0xffffffffu, s0, 2);
    s1 += __shfl_xor_sync(0xffffffffu, s1, 1);
    s1 += __shfl_xor_sync(0xffffffffu, s1, 2);
    const float inv0 = 1.f / s0;
    const float inv1 = 1.f / s1;

    float o[4][4];
#pragma unroll
    for (int dt = 0; dt < 4; ++dt)
#pragma unroll
        for (int r = 0; r < 4; ++r) o[dt][r] = 0.f;

#pragma unroll
    for (int kc = 0; kc < 4; ++kc) {
        uint32_t ph_[4], pl_[4];
        const int t0 = kc * 2, t1 = kc * 2 + 1;
        split2(s[t0][0], s[t0][1], ph_[0], pl_[0]);
        split2(s[t0][2], s[t0][3], ph_[1], pl_[1]);
        if (t1 < 7) {
            split2(s[t1][0], s[t1][1], ph_[2], pl_[2]);
            split2(s[t1][2], s[t1][3], ph_[3], pl_[3]);
        } else {
            ph_[2] = ph_[3] = pl_[2] = pl_[3] = 0u;
        }

        uint32_t vh_[4][2], vl_[4][2];
#pragma unroll
        for (int dp = 0; dp < 2; ++dp) {
            const uint32_t off = (uint32_t)(((kc*16 + vRowOff) * SPAD + dp*16 + vColOff) * 2);
            uint32_t r0_, r1_, r2_, r3_;
            ldm_x4_t(r0_, r1_, r2_, r3_, uVh + off);
            vh_[dp*2][0] = r0_; vh_[dp*2][1] = r1_; vh_[dp*2+1][0] = r2_; vh_[dp*2+1][1] = r3_;
            ldm_x4_t(r0_, r1_, r2_, r3_, uVl + off);
            vl_[dp*2][0] = r0_; vl_[dp*2][1] = r1_; vl_[dp*2+1][0] = r2_; vl_[dp*2+1][1] = r3_;
        }
#pragma unroll
        for (int dt = 0; dt < 4; ++dt) {
            mma_bf16(o[dt], ph_[0], ph_[1], ph_[2], ph_[3], vh_[dt][0], vh_[dt][1]);
            mma_bf16(o[dt], pl_[0], pl_[1], pl_[2], pl_[3], vh_[dt][0], vh_[dt][1]);
            mma_bf16(o[dt], ph_[0], ph_[1], ph_[2], ph_[3], vl_[dt][0], vl_[dt][1]);
        }
    }

#pragma unroll
    for (int dt = 0; dt < 4; ++dt) {
        const int d = dt * 8 + lc * 2;
        if (r0 < NTOK) {
            float2 o2;
            o2.x = o[dt][0] * inv0;
            o2.y = o[dt][1] * inv0;
            *(float2*)(g_att + (b * NTOK + r0) * EMB + h * 32 + d) = o2;
        }
        if (r0 + 8 < NTOK) {
            float2 o2;
            o2.x = o[dt][2] * inv1;
            o2.y = o[dt][3] * inv1;
            *(float2*)(g_att + (b * NTOK + r0 + 8) * EMB + h * 32 + d) = o2;
        }
    }
}

// ---------------------------------------------------------------------------
extern "C" void kernel_launch(void* const* d_in, const int* in_sizes, int n_in,
                              void* d_out, int out_size)
{
    const float* x          = (const float*)d_in[0];
    const float* mask       = (const float*)d_in[1];
    const float* qkv_w      = (const float*)d_in[2];
    const float* qkv_b      = (const float*)d_in[3];
    const float* proj_w     = (const float*)d_in[4];
    const float* proj_b     = (const float*)d_in[5];
    const float* bias_table = (const float*)d_in[6];
    float* out = (float*)d_out;

    uint4* fq = nullptr; uint4* fp = nullptr;
    cudaGetSymbolAddress((void**)&fq, g_fq);
    cudaGetSymbolAddress((void**)&fp, g_fp);

    cudaFuncSetAttribute(gemm1_hmma, cudaFuncAttributeMaxDynamicSharedMemorySize, SMEM_BYTES);
    cudaFuncSetAttribute(attn_hmma,  cudaFuncAttributeMaxDynamicSharedMemorySize, ATTN_SMEM);

    prep_all<<<576, 256>>>(mask, bias_table, qkv_w, proj_w, fq, fp);
    prep_x<<<MTILES, 256>>>(x);
    gemm0_frag<<<dim3(768 / 96, MROWS / 128), 128>>>(qkv_b);
    attn_hmma<<<BQ * NHEADS, 128, ATTN_SMEM>>>();
    gemm1_hmma<<<dim3(EMB / 128, MROWS / 128), 256, SMEM_BYTES>>>(proj_b, out);
}